// round 9
// baseline (speedup 1.0000x reference)
#include <cuda_runtime.h>
#include <cuda_bf16.h>
#include <cstdint>

// word2vec negative-sampling loss:
//   second_emb  [200000, 128] f32   (low reuse  -> L2 evict_first)
//   context_emb [200000, 128] f32   (~3.9x reuse -> L2 evict_last)
//   v_i, v_j    [131072] i32
//   negsamples  [5, 131072] i32
// out: scalar f32 = -mean_b( logsig(vi.vj) + sum_k logsig(-vi.neg_k) )
//
// Single kernel, NO fence / NO release atomics (both measured as large
// regressions on sm_103a: gpu-scope fence = CCTL.IVALL L1 flush; release
// atomic also regressed). Completion protocol = ONE relaxed packed-u64
// atomicAdd per block: high 14 bits count blocks, low 50 bits accumulate a
// bias-shifted fixed-point partial. Integer adds are order-independent ->
// bit-deterministic. The block seeing count==grid-1 holds the full sum in
// the atomic's RETURN VALUE (atomicity = no fence needed) and writes out.

#define EMBED 128
#define NUM_NEG 5
#define TPB 512
#define WPB 16                      // warps per block

#define CNT_SHIFT 50
#define LOW_MASK  ((1ull << CNT_SHIFT) - 1ull)
#define FIX_SCALE 1048576.0         // 2^20
#define FIX_BIAS  4096.0            // per-block bias, keeps contributions > 0

__device__ unsigned long long g_accum = 0ull;

__device__ __forceinline__ float fast_log_sigmoid(float x) {
    return fminf(x, 0.0f) - __logf(1.0f + __expf(-fabsf(x)));
}

__device__ __forceinline__ float dot4(float4 a, float4 b) {
    return fmaf(a.x, b.x, fmaf(a.y, b.y, fmaf(a.z, b.z, a.w * b.w)));
}

__device__ __forceinline__ uint64_t mk_policy_evict_first() {
    uint64_t p;
    asm("createpolicy.fractional.L2::evict_first.b64 %0, 1.0;" : "=l"(p));
    return p;
}

__device__ __forceinline__ uint64_t mk_policy_evict_last() {
    uint64_t p;
    asm("createpolicy.fractional.L2::evict_last.b64 %0, 1.0;" : "=l"(p));
    return p;
}

__device__ __forceinline__ float4 ldg_hint(const float4* p, uint64_t policy) {
    float4 v;
    asm volatile("ld.global.nc.L2::cache_hint.v4.f32 {%0,%1,%2,%3}, [%4], %5;"
                 : "=f"(v.x), "=f"(v.y), "=f"(v.z), "=f"(v.w)
                 : "l"(p), "l"(policy));
    return v;
}

__global__ void __launch_bounds__(TPB)
w2v_main(const float* __restrict__ second_emb,
         const float* __restrict__ context_emb,
         const int* __restrict__ v_i,
         const int* __restrict__ v_j,
         const int* __restrict__ negs,
         int batch, float inv_batch,
         float* __restrict__ out)
{
    const int lane = threadIdx.x & 31;
    const int wid  = threadIdx.x >> 5;
    const int e    = blockIdx.x * WPB + wid;    // one element per warp

    float elem_loss = 0.0f;   // valid on lane 0

    if (e < batch) {
        const uint64_t pol_stream   = mk_policy_evict_first();
        const uint64_t pol_resident = mk_policy_evict_last();

        // ---- lane-distributed index gather: ONE LDG for all 7 indices ----
        int myidx = 0;
        if (lane < 7) {
            const int* p;
            if (lane == 0)      p = v_i + e;
            else if (lane == 1) p = v_j + e;
            else                p = negs + (lane - 2) * batch + e;
            myidx = __ldg(p);
        }
        const int ivi = __shfl_sync(0xFFFFFFFFu, myidx, 0);
        const int ivj = __shfl_sync(0xFFFFFFFFu, myidx, 1);
        int ineg[NUM_NEG];
        #pragma unroll
        for (int k = 0; k < NUM_NEG; k++)
            ineg[k] = __shfl_sync(0xFFFFFFFFu, myidx, k + 2);

        // 32-bit row offsets (200000*128 < 2^31)
        const float4* vi_row = reinterpret_cast<const float4*>(
            second_emb + (unsigned)ivi * EMBED);
        float4 a = ldg_hint(&vi_row[lane], pol_stream);

        // all 6 context rows issued before consumption (MLP)
        float4 r[NUM_NEG + 1];
        const float4* vj_row = reinterpret_cast<const float4*>(
            context_emb + (unsigned)ivj * EMBED);
        r[0] = ldg_hint(&vj_row[lane], pol_resident);
        #pragma unroll
        for (int k = 0; k < NUM_NEG; k++) {
            const float4* nrow = reinterpret_cast<const float4*>(
                context_emb + (unsigned)ineg[k] * EMBED);
            r[k + 1] = ldg_hint(&nrow[lane], pol_resident);
        }

        float d[NUM_NEG + 1];
        #pragma unroll
        for (int j = 0; j < NUM_NEG + 1; j++)
            d[j] = dot4(a, r[j]);

        // split-butterfly: 21 shuffles instead of 30
        #pragma unroll
        for (int j = 0; j < 6; j++)
            d[j] += __shfl_xor_sync(0xFFFFFFFFu, d[j], 16);

        const bool hi = lane >= 16;
        float v0 = hi ? d[3] : d[0];
        float v1 = hi ? d[4] : d[1];
        float v2 = hi ? d[5] : d[2];

        #pragma unroll
        for (int off = 8; off > 0; off >>= 1) {
            v0 += __shfl_xor_sync(0xFFFFFFFFu, v0, off);
            v1 += __shfl_xor_sync(0xFFFFFFFFu, v1, off);
            v2 += __shfl_xor_sync(0xFFFFFFFFu, v2, off);
        }

        // distributed logsig: lanes {0,1,2,16,17,18} each own one term
        const int sl = lane & 15;
        float x = v0;
        x = (sl == 1) ? v1 : x;
        x = (sl == 2) ? v2 : x;
        float arg = (lane == 0) ? x : -x;
        float t = fast_log_sigmoid(arg);
        t = (sl < 3) ? t : 0.0f;

        t += __shfl_xor_sync(0xFFFFFFFFu, t, 16);
        t += __shfl_xor_sync(0xFFFFFFFFu, t, 1);
        t += __shfl_xor_sync(0xFFFFFFFFu, t, 2);
        elem_loss = t;                          // lane 0 holds element loss
    }

    // ---- block reduce (deterministic fixed tree): 16 warps -> 1 value ----
    __shared__ float ws[WPB];
    if (lane == 0)
        ws[wid] = elem_loss;
    __syncthreads();

    if (threadIdx.x < 32) {
        float s = (threadIdx.x < WPB) ? ws[threadIdx.x] : 0.0f;
        #pragma unroll
        for (int off = 8; off > 0; off >>= 1)
            s += __shfl_xor_sync(0xFFFFFFFFu, s, off);

        if (threadIdx.x == 0) {
            // quantize in double: (s + BIAS) * 2^20, always positive,
            // max 2^32 per block; 8192 blocks < 2^45 << 2^50 field.
            double ds = (double)s + FIX_BIAS;
            unsigned long long enc =
                (unsigned long long)__double2ll_rn(ds * FIX_SCALE);
            unsigned long long packed = (1ull << CNT_SHIFT) | enc;

            // relaxed atomic: no fence, order-independent integer sum
            unsigned long long old = atomicAdd(&g_accum, packed);

            if ((old >> CNT_SHIFT) == (unsigned long long)(gridDim.x - 1)) {
                // we are provably the last block: old already contains every
                // other block's contribution (atomicity), add ours.
                unsigned long long tot = (old & LOW_MASK) + enc;
                double sum = (double)tot / FIX_SCALE
                           - (double)gridDim.x * FIX_BIAS;
                out[0] = -(float)(sum * (double)inv_batch);
                g_accum = 0ull;   // reset for next graph replay (no racer:
                                  // all blocks' atomics already completed)
            }
        }
    }
}

extern "C" void kernel_launch(void* const* d_in, const int* in_sizes, int n_in,
                              void* d_out, int out_size)
{
    const float* second_emb  = (const float*)d_in[0];
    const float* context_emb = (const float*)d_in[1];
    const int*   v_i         = (const int*)d_in[2];
    const int*   v_j         = (const int*)d_in[3];
    const int*   negs        = (const int*)d_in[4];

    const int batch  = in_sizes[2];                 // 131072
    const int blocks = (batch + WPB - 1) / WPB;     // 8192

    w2v_main<<<blocks, TPB>>>(second_emb, context_emb, v_i, v_j, negs,
                              batch, 1.0f / (float)batch, (float*)d_out);
}

// round 10
// speedup vs baseline: 1.2448x; 1.2448x over previous
#include <cuda_runtime.h>
#include <cuda_bf16.h>
#include <cstdint>

// word2vec negative-sampling loss:
//   second_emb  [200000, 128] f32   (low reuse   -> L2 evict_first)
//   context_emb [200000, 128] f32   (~3.9x reuse -> L2 evict_last)
//   v_i, v_j    [131072] i32
//   negsamples  [5, 131072] i32
// out: scalar f32 = -mean_b( logsig(vi.vj) + sum_k logsig(-vi.neg_k) )
//
// Structure lessons (measured, 4 failed fusions): NO cross-block protocol
// survives on sm_103a for this kernel — gpu fence = CCTL.IVALL L1 flush
// (R2/R3), release atomic regressed (R6), even one relaxed packed atomicAdd
// per block regressed 35us (R9: LTS atomic ALU serializes per address).
// => two kernels, with PDL overlapping the reduce launch into main's drain.

#define EMBED 128
#define NUM_NEG 5
#define TPB 512
#define WPB 16                      // warps per block
#define NPART 8192                  // batch / WPB for batch=131072

__device__ float g_partials[NPART];

__device__ __forceinline__ float fast_log_sigmoid(float x) {
    // logsig(x) = min(x,0) - log(1 + exp(-|x|))
    return fminf(x, 0.0f) - __logf(1.0f + __expf(-fabsf(x)));
}

__device__ __forceinline__ float dot4(float4 a, float4 b) {
    return fmaf(a.x, b.x, fmaf(a.y, b.y, fmaf(a.z, b.z, a.w * b.w)));
}

__device__ __forceinline__ uint64_t mk_policy_evict_first() {
    uint64_t p;
    asm("createpolicy.fractional.L2::evict_first.b64 %0, 1.0;" : "=l"(p));
    return p;
}

__device__ __forceinline__ uint64_t mk_policy_evict_last() {
    uint64_t p;
    asm("createpolicy.fractional.L2::evict_last.b64 %0, 1.0;" : "=l"(p));
    return p;
}

__device__ __forceinline__ float4 ldg_hint(const float4* p, uint64_t policy) {
    float4 v;
    asm volatile("ld.global.nc.L2::cache_hint.v4.f32 {%0,%1,%2,%3}, [%4], %5;"
                 : "=f"(v.x), "=f"(v.y), "=f"(v.z), "=f"(v.w)
                 : "l"(p), "l"(policy));
    return v;
}

__global__ void __launch_bounds__(TPB)
w2v_main(const float* __restrict__ second_emb,
         const float* __restrict__ context_emb,
         const int* __restrict__ v_i,
         const int* __restrict__ v_j,
         const int* __restrict__ negs,
         int batch)
{
    const int lane = threadIdx.x & 31;
    const int wid  = threadIdx.x >> 5;
    const int e    = blockIdx.x * WPB + wid;    // one element per warp
                                                // (grid exactly tiles batch)

    const uint64_t pol_stream   = mk_policy_evict_first();
    const uint64_t pol_resident = mk_policy_evict_last();

    // ---- lane-distributed index gather: ONE LDG for all 7 indices ----
    int myidx = 0;
    if (lane < 7) {
        const int* p;
        if (lane == 0)      p = v_i + e;
        else if (lane == 1) p = v_j + e;
        else                p = negs + (lane - 2) * batch + e;
        myidx = __ldg(p);
    }
    const int ivi = __shfl_sync(0xFFFFFFFFu, myidx, 0);
    const int ivj = __shfl_sync(0xFFFFFFFFu, myidx, 1);
    int ineg[NUM_NEG];
    #pragma unroll
    for (int k = 0; k < NUM_NEG; k++)
        ineg[k] = __shfl_sync(0xFFFFFFFFu, myidx, k + 2);

    // 32-bit row offsets (200000*128 < 2^31)
    const float4* vi_row = reinterpret_cast<const float4*>(
        second_emb + (unsigned)ivi * EMBED);
    float4 a = ldg_hint(&vi_row[lane], pol_stream);

    // all 6 context rows issued before consumption (MLP)
    float4 r[NUM_NEG + 1];
    const float4* vj_row = reinterpret_cast<const float4*>(
        context_emb + (unsigned)ivj * EMBED);
    r[0] = ldg_hint(&vj_row[lane], pol_resident);
    #pragma unroll
    for (int k = 0; k < NUM_NEG; k++) {
        const float4* nrow = reinterpret_cast<const float4*>(
            context_emb + (unsigned)ineg[k] * EMBED);
        r[k + 1] = ldg_hint(&nrow[lane], pol_resident);
    }

    float d[NUM_NEG + 1];
    #pragma unroll
    for (int j = 0; j < NUM_NEG + 1; j++)
        d[j] = dot4(a, r[j]);

    // split-butterfly: fold halves once, then each half-warp finishes
    // 3 of the 6 dot reductions (21 shuffles instead of 30)
    #pragma unroll
    for (int j = 0; j < 6; j++)
        d[j] += __shfl_xor_sync(0xFFFFFFFFu, d[j], 16);

    const bool hi = lane >= 16;
    float v0 = hi ? d[3] : d[0];
    float v1 = hi ? d[4] : d[1];
    float v2 = hi ? d[5] : d[2];

    #pragma unroll
    for (int off = 8; off > 0; off >>= 1) {
        v0 += __shfl_xor_sync(0xFFFFFFFFu, v0, off);
        v1 += __shfl_xor_sync(0xFFFFFFFFu, v1, off);
        v2 += __shfl_xor_sync(0xFFFFFFFFu, v2, off);
    }
    // low half lanes hold D0,D1,D2; high half D3,D4,D5 (replicated)

    // distributed logsig: lanes {0,1,2,16,17,18} each own one term
    const int sl = lane & 15;
    float x = v0;
    x = (sl == 1) ? v1 : x;
    x = (sl == 2) ? v2 : x;
    float arg = (lane == 0) ? x : -x;      // positive term only for D0
    float t = fast_log_sigmoid(arg);
    t = (sl < 3) ? t : 0.0f;

    t += __shfl_xor_sync(0xFFFFFFFFu, t, 16);
    t += __shfl_xor_sync(0xFFFFFFFFu, t, 1);
    t += __shfl_xor_sync(0xFFFFFFFFu, t, 2);
    const float elem_loss = t;             // lane 0 holds element loss

    // block reduce (deterministic): 16 warp values -> 1 partial
    __shared__ float ws[WPB];
    if (lane == 0)
        ws[wid] = elem_loss;
    __syncthreads();

    if (threadIdx.x < 32) {
        float s = (threadIdx.x < WPB) ? ws[threadIdx.x] : 0.0f;
        #pragma unroll
        for (int off = 8; off > 0; off >>= 1)
            s += __shfl_xor_sync(0xFFFFFFFFu, s, off);
        if (threadIdx.x == 0)
            g_partials[blockIdx.x] = s;
    }
}

__global__ void __launch_bounds__(1024)
w2v_reduce(float* __restrict__ out, float inv_batch)
{
    // PDL: this block is resident while w2v_main drains; wait gives full
    // completion + memory-visibility semantics for g_partials.
    cudaGridDependencySynchronize();

    // 8192 partials = 2048 float4; 1024 threads x 2 independent float4 each
    const float4* p = reinterpret_cast<const float4*>(g_partials);
    const int tid = threadIdx.x;

    float4 u = __ldg(&p[tid]);
    float4 v = __ldg(&p[tid + 1024]);
    float s = ((u.x + u.y) + (u.z + u.w)) + ((v.x + v.y) + (v.z + v.w));

    #pragma unroll
    for (int off = 16; off > 0; off >>= 1)
        s += __shfl_xor_sync(0xFFFFFFFFu, s, off);

    __shared__ float sh[32];
    if ((tid & 31) == 0)
        sh[tid >> 5] = s;
    __syncthreads();

    if (tid < 32) {
        float t = sh[tid];
        #pragma unroll
        for (int off = 16; off > 0; off >>= 1)
            t += __shfl_xor_sync(0xFFFFFFFFu, t, off);
        if (tid == 0)
            out[0] = -t * inv_batch;
    }
}

extern "C" void kernel_launch(void* const* d_in, const int* in_sizes, int n_in,
                              void* d_out, int out_size)
{
    const float* second_emb  = (const float*)d_in[0];
    const float* context_emb = (const float*)d_in[1];
    const int*   v_i         = (const int*)d_in[2];
    const int*   v_j         = (const int*)d_in[3];
    const int*   negs        = (const int*)d_in[4];

    const int batch  = in_sizes[2];                 // 131072
    const int blocks = (batch + WPB - 1) / WPB;     // 8192

    w2v_main<<<blocks, TPB>>>(second_emb, context_emb, v_i, v_j, negs, batch);

    // PDL launch: reduce kernel is scheduled while main drains.
    cudaLaunchConfig_t cfg = {};
    cfg.gridDim  = dim3(1, 1, 1);
    cfg.blockDim = dim3(1024, 1, 1);
    cudaLaunchAttribute attr[1];
    attr[0].id = cudaLaunchAttributeProgrammaticStreamSerialization;
    attr[0].val.programmaticStreamSerializationAllowed = 1;
    cfg.attrs = attr;
    cfg.numAttrs = 1;
    float inv_batch = 1.0f / (float)batch;
    cudaLaunchKernelEx(&cfg, w2v_reduce, (float*)d_out, inv_batch);
}

// round 11
// speedup vs baseline: 1.6335x; 1.3122x over previous
#include <cuda_runtime.h>
#include <cuda_bf16.h>
#include <cstdint>

// word2vec negative-sampling loss:
//   second_emb  [200000, 128] f32   (low reuse   -> L2 evict_first)
//   context_emb [200000, 128] f32   (~3.9x reuse -> L2 evict_last)
//   v_i, v_j    [131072] i32
//   negsamples  [5, 131072] i32
// out: scalar f32 = -mean_b( logsig(vi.vj) + sum_k logsig(-vi.neg_k) )
//
// Structure (FINAL after 5 failed alternatives): plain two-kernel split.
//  - gpu fence = CCTL.IVALL L1 flush (R2/R3 regression)
//  - release atomic protocol (R6 regression)
//  - relaxed packed atomicAdd, 1/block (R9: +35us, LTS atomic serialization)
//  - PDL pre-scheduled reduce (R10: +18us, co-residency interference)
// Main kernel change this round: __launch_bounds__(512, 4) -> 32 regs,
// 4 blocks/SM, 100% occupancy (was 34 regs -> 3 blocks/SM -> 75%).

#define EMBED 128
#define NUM_NEG 5
#define TPB 512
#define WPB 16                      // warps per block
#define NPART 8192                  // batch / WPB for batch=131072

__device__ float g_partials[NPART];

__device__ __forceinline__ float fast_log_sigmoid(float x) {
    // logsig(x) = min(x,0) - log(1 + exp(-|x|))
    return fminf(x, 0.0f) - __logf(1.0f + __expf(-fabsf(x)));
}

__device__ __forceinline__ float dot4(float4 a, float4 b) {
    return fmaf(a.x, b.x, fmaf(a.y, b.y, fmaf(a.z, b.z, a.w * b.w)));
}

__device__ __forceinline__ uint64_t mk_policy_evict_first() {
    uint64_t p;
    asm("createpolicy.fractional.L2::evict_first.b64 %0, 1.0;" : "=l"(p));
    return p;
}

__device__ __forceinline__ uint64_t mk_policy_evict_last() {
    uint64_t p;
    asm("createpolicy.fractional.L2::evict_last.b64 %0, 1.0;" : "=l"(p));
    return p;
}

__device__ __forceinline__ float4 ldg_hint(const float4* p, uint64_t policy) {
    float4 v;
    asm volatile("ld.global.nc.L2::cache_hint.v4.f32 {%0,%1,%2,%3}, [%4], %5;"
                 : "=f"(v.x), "=f"(v.y), "=f"(v.z), "=f"(v.w)
                 : "l"(p), "l"(policy));
    return v;
}

__global__ void __launch_bounds__(TPB, 4)
w2v_main(const float* __restrict__ second_emb,
         const float* __restrict__ context_emb,
         const int* __restrict__ v_i,
         const int* __restrict__ v_j,
         const int* __restrict__ negs,
         int batch)
{
    const int lane = threadIdx.x & 31;
    const int wid  = threadIdx.x >> 5;
    const int e    = blockIdx.x * WPB + wid;    // one element per warp
                                                // (grid exactly tiles batch)

    const uint64_t pol_stream   = mk_policy_evict_first();
    const uint64_t pol_resident = mk_policy_evict_last();

    // ---- lane-distributed index gather: ONE LDG for all 7 indices ----
    int myidx = 0;
    if (lane < 7) {
        const int* p;
        if (lane == 0)      p = v_i + e;
        else if (lane == 1) p = v_j + e;
        else                p = negs + (lane - 2) * batch + e;
        myidx = __ldg(p);
    }
    const int ivi = __shfl_sync(0xFFFFFFFFu, myidx, 0);
    const int ivj = __shfl_sync(0xFFFFFFFFu, myidx, 1);
    int ineg[NUM_NEG];
    #pragma unroll
    for (int k = 0; k < NUM_NEG; k++)
        ineg[k] = __shfl_sync(0xFFFFFFFFu, myidx, k + 2);

    // 32-bit row offsets (200000*128 < 2^31)
    const float4* vi_row = reinterpret_cast<const float4*>(
        second_emb + (unsigned)ivi * EMBED);
    float4 a = ldg_hint(&vi_row[lane], pol_stream);

    // all 6 context rows issued before consumption (MLP)
    float4 r[NUM_NEG + 1];
    const float4* vj_row = reinterpret_cast<const float4*>(
        context_emb + (unsigned)ivj * EMBED);
    r[0] = ldg_hint(&vj_row[lane], pol_resident);
    #pragma unroll
    for (int k = 0; k < NUM_NEG; k++) {
        const float4* nrow = reinterpret_cast<const float4*>(
            context_emb + (unsigned)ineg[k] * EMBED);
        r[k + 1] = ldg_hint(&nrow[lane], pol_resident);
    }

    float d[NUM_NEG + 1];
    #pragma unroll
    for (int j = 0; j < NUM_NEG + 1; j++)
        d[j] = dot4(a, r[j]);

    // split-butterfly: fold halves once, then each half-warp finishes
    // 3 of the 6 dot reductions (21 shuffles instead of 30)
    #pragma unroll
    for (int j = 0; j < 6; j++)
        d[j] += __shfl_xor_sync(0xFFFFFFFFu, d[j], 16);

    const bool hi = lane >= 16;
    float v0 = hi ? d[3] : d[0];
    float v1 = hi ? d[4] : d[1];
    float v2 = hi ? d[5] : d[2];

    #pragma unroll
    for (int off = 8; off > 0; off >>= 1) {
        v0 += __shfl_xor_sync(0xFFFFFFFFu, v0, off);
        v1 += __shfl_xor_sync(0xFFFFFFFFu, v1, off);
        v2 += __shfl_xor_sync(0xFFFFFFFFu, v2, off);
    }
    // low half lanes hold D0,D1,D2; high half D3,D4,D5 (replicated)

    // distributed logsig: lanes {0,1,2,16,17,18} each own one term
    const int sl = lane & 15;
    float x = v0;
    x = (sl == 1) ? v1 : x;
    x = (sl == 2) ? v2 : x;
    float arg = (lane == 0) ? x : -x;      // positive term only for D0
    float t = fast_log_sigmoid(arg);
    t = (sl < 3) ? t : 0.0f;

    t += __shfl_xor_sync(0xFFFFFFFFu, t, 16);
    t += __shfl_xor_sync(0xFFFFFFFFu, t, 1);
    t += __shfl_xor_sync(0xFFFFFFFFu, t, 2);
    const float elem_loss = t;             // lane 0 holds element loss

    // block reduce (deterministic): 16 warp values -> 1 partial
    __shared__ float ws[WPB];
    if (lane == 0)
        ws[wid] = elem_loss;
    __syncthreads();

    if (threadIdx.x < 32) {
        float s = (threadIdx.x < WPB) ? ws[threadIdx.x] : 0.0f;
        #pragma unroll
        for (int off = 8; off > 0; off >>= 1)
            s += __shfl_xor_sync(0xFFFFFFFFu, s, off);
        if (threadIdx.x == 0)
            g_partials[blockIdx.x] = s;
    }
}

__global__ void __launch_bounds__(1024)
w2v_reduce(float* __restrict__ out, float inv_batch)
{
    // 8192 partials = 2048 float4; 1024 threads x 2 independent float4 each
    const float4* p = reinterpret_cast<const float4*>(g_partials);
    const int tid = threadIdx.x;

    float4 u = __ldg(&p[tid]);
    float4 v = __ldg(&p[tid + 1024]);
    float s = ((u.x + u.y) + (u.z + u.w)) + ((v.x + v.y) + (v.z + v.w));

    #pragma unroll
    for (int off = 16; off > 0; off >>= 1)
        s += __shfl_xor_sync(0xFFFFFFFFu, s, off);

    __shared__ float sh[32];
    if ((tid & 31) == 0)
        sh[tid >> 5] = s;
    __syncthreads();

    if (tid < 32) {
        float t = sh[tid];
        #pragma unroll
        for (int off = 16; off > 0; off >>= 1)
            t += __shfl_xor_sync(0xFFFFFFFFu, t, off);
        if (tid == 0)
            out[0] = -t * inv_batch;
    }
}

extern "C" void kernel_launch(void* const* d_in, const int* in_sizes, int n_in,
                              void* d_out, int out_size)
{
    const float* second_emb  = (const float*)d_in[0];
    const float* context_emb = (const float*)d_in[1];
    const int*   v_i         = (const int*)d_in[2];
    const int*   v_j         = (const int*)d_in[3];
    const int*   negs        = (const int*)d_in[4];

    const int batch  = in_sizes[2];                 // 131072
    const int blocks = (batch + WPB - 1) / WPB;     // 8192

    w2v_main<<<blocks, TPB>>>(second_emb, context_emb, v_i, v_j, negs, batch);
    w2v_reduce<<<1, 1024>>>((float*)d_out, 1.0f / (float)batch);
}

// round 12
// speedup vs baseline: 1.7429x; 1.0670x over previous
#include <cuda_runtime.h>
#include <cuda_bf16.h>
#include <cstdint>

// word2vec negative-sampling loss:
//   second_emb  [200000, 128] f32   (low reuse   -> L2 evict_first)
//   context_emb [200000, 128] f32   (~3.9x reuse -> L2 evict_last)
//   v_i, v_j    [131072] i32
//   negsamples  [5, 131072] i32
// out: scalar f32 = -mean_b( logsig(vi.vj) + sum_k logsig(-vi.neg_k) )
//
// Structure (FINAL after 5 failed alternatives): plain two-kernel split.
//  - gpu fence = CCTL.IVALL L1 flush (R2/R3 regression)
//  - release atomic protocol (R6 regression)
//  - relaxed packed atomicAdd, 1/block (R9: +35us, LTS atomic serialization)
//  - PDL pre-scheduled reduce (R10: +18us, co-residency interference)
//  - forced reg cap (R11: spills, +0.7us)
// This round: TPB=256 -> 7 blocks/SM at natural 34 regs = 56 warps (87.5%)
// vs 48 warps (75%) at TPB=512. More resident gathers against the LTS cap.

#define EMBED 128
#define NUM_NEG 5
#define TPB 256
#define WPB 8                       // warps per block
#define NPART 16384                 // batch / WPB for batch=131072

__device__ float g_partials[NPART];

__device__ __forceinline__ float fast_log_sigmoid(float x) {
    // logsig(x) = min(x,0) - log(1 + exp(-|x|))
    return fminf(x, 0.0f) - __logf(1.0f + __expf(-fabsf(x)));
}

__device__ __forceinline__ float dot4(float4 a, float4 b) {
    return fmaf(a.x, b.x, fmaf(a.y, b.y, fmaf(a.z, b.z, a.w * b.w)));
}

__device__ __forceinline__ uint64_t mk_policy_evict_first() {
    uint64_t p;
    asm("createpolicy.fractional.L2::evict_first.b64 %0, 1.0;" : "=l"(p));
    return p;
}

__device__ __forceinline__ uint64_t mk_policy_evict_last() {
    uint64_t p;
    asm("createpolicy.fractional.L2::evict_last.b64 %0, 1.0;" : "=l"(p));
    return p;
}

__device__ __forceinline__ float4 ldg_hint(const float4* p, uint64_t policy) {
    float4 v;
    asm volatile("ld.global.nc.L2::cache_hint.v4.f32 {%0,%1,%2,%3}, [%4], %5;"
                 : "=f"(v.x), "=f"(v.y), "=f"(v.z), "=f"(v.w)
                 : "l"(p), "l"(policy));
    return v;
}

__global__ void __launch_bounds__(TPB)
w2v_main(const float* __restrict__ second_emb,
         const float* __restrict__ context_emb,
         const int* __restrict__ v_i,
         const int* __restrict__ v_j,
         const int* __restrict__ negs,
         int batch)
{
    const int lane = threadIdx.x & 31;
    const int wid  = threadIdx.x >> 5;
    const int e    = blockIdx.x * WPB + wid;    // one element per warp
                                                // (grid exactly tiles batch)

    const uint64_t pol_stream   = mk_policy_evict_first();
    const uint64_t pol_resident = mk_policy_evict_last();

    // ---- lane-distributed index gather: ONE LDG for all 7 indices ----
    int myidx = 0;
    if (lane < 7) {
        const int* p;
        if (lane == 0)      p = v_i + e;
        else if (lane == 1) p = v_j + e;
        else                p = negs + (lane - 2) * batch + e;
        myidx = __ldg(p);
    }
    const int ivi = __shfl_sync(0xFFFFFFFFu, myidx, 0);
    const int ivj = __shfl_sync(0xFFFFFFFFu, myidx, 1);
    int ineg[NUM_NEG];
    #pragma unroll
    for (int k = 0; k < NUM_NEG; k++)
        ineg[k] = __shfl_sync(0xFFFFFFFFu, myidx, k + 2);

    // 32-bit row offsets (200000*128 < 2^31)
    const float4* vi_row = reinterpret_cast<const float4*>(
        second_emb + (unsigned)ivi * EMBED);
    float4 a = ldg_hint(&vi_row[lane], pol_stream);

    // all 6 context rows issued before consumption (MLP)
    float4 r[NUM_NEG + 1];
    const float4* vj_row = reinterpret_cast<const float4*>(
        context_emb + (unsigned)ivj * EMBED);
    r[0] = ldg_hint(&vj_row[lane], pol_resident);
    #pragma unroll
    for (int k = 0; k < NUM_NEG; k++) {
        const float4* nrow = reinterpret_cast<const float4*>(
            context_emb + (unsigned)ineg[k] * EMBED);
        r[k + 1] = ldg_hint(&nrow[lane], pol_resident);
    }

    float d[NUM_NEG + 1];
    #pragma unroll
    for (int j = 0; j < NUM_NEG + 1; j++)
        d[j] = dot4(a, r[j]);

    // split-butterfly: fold halves once, then each half-warp finishes
    // 3 of the 6 dot reductions (21 shuffles instead of 30)
    #pragma unroll
    for (int j = 0; j < 6; j++)
        d[j] += __shfl_xor_sync(0xFFFFFFFFu, d[j], 16);

    const bool hi = lane >= 16;
    float v0 = hi ? d[3] : d[0];
    float v1 = hi ? d[4] : d[1];
    float v2 = hi ? d[5] : d[2];

    #pragma unroll
    for (int off = 8; off > 0; off >>= 1) {
        v0 += __shfl_xor_sync(0xFFFFFFFFu, v0, off);
        v1 += __shfl_xor_sync(0xFFFFFFFFu, v1, off);
        v2 += __shfl_xor_sync(0xFFFFFFFFu, v2, off);
    }
    // low half lanes hold D0,D1,D2; high half D3,D4,D5 (replicated)

    // distributed logsig: lanes {0,1,2,16,17,18} each own one term
    const int sl = lane & 15;
    float x = v0;
    x = (sl == 1) ? v1 : x;
    x = (sl == 2) ? v2 : x;
    float arg = (lane == 0) ? x : -x;      // positive term only for D0
    float t = fast_log_sigmoid(arg);
    t = (sl < 3) ? t : 0.0f;

    t += __shfl_xor_sync(0xFFFFFFFFu, t, 16);
    t += __shfl_xor_sync(0xFFFFFFFFu, t, 1);
    t += __shfl_xor_sync(0xFFFFFFFFu, t, 2);
    const float elem_loss = t;             // lane 0 holds element loss

    // block reduce (deterministic): 8 warp values -> 1 partial
    __shared__ float ws[WPB];
    if (lane == 0)
        ws[wid] = elem_loss;
    __syncthreads();

    if (threadIdx.x < 32) {
        float s = (threadIdx.x < WPB) ? ws[threadIdx.x] : 0.0f;
        #pragma unroll
        for (int off = 4; off > 0; off >>= 1)
            s += __shfl_xor_sync(0xFFFFFFFFu, s, off);
        if (threadIdx.x == 0)
            g_partials[blockIdx.x] = s;
    }
}

__global__ void __launch_bounds__(1024)
w2v_reduce(float* __restrict__ out, float inv_batch)
{
    // 16384 partials = 4096 float4; 1024 threads x 4 independent float4
    const float4* p = reinterpret_cast<const float4*>(g_partials);
    const int tid = threadIdx.x;

    float4 s4 = make_float4(0.f, 0.f, 0.f, 0.f);
    #pragma unroll
    for (int i = 0; i < 4; i++) {
        float4 v = __ldg(&p[tid + i * 1024]);
        s4.x += v.x; s4.y += v.y; s4.z += v.z; s4.w += v.w;
    }
    float s = (s4.x + s4.y) + (s4.z + s4.w);

    #pragma unroll
    for (int off = 16; off > 0; off >>= 1)
        s += __shfl_xor_sync(0xFFFFFFFFu, s, off);

    __shared__ float sh[32];
    if ((tid & 31) == 0)
        sh[tid >> 5] = s;
    __syncthreads();

    if (tid < 32) {
        float t = sh[tid];
        #pragma unroll
        for (int off = 16; off > 0; off >>= 1)
            t += __shfl_xor_sync(0xFFFFFFFFu, t, off);
        if (tid == 0)
            out[0] = -t * inv_batch;
    }
}

extern "C" void kernel_launch(void* const* d_in, const int* in_sizes, int n_in,
                              void* d_out, int out_size)
{
    const float* second_emb  = (const float*)d_in[0];
    const float* context_emb = (const float*)d_in[1];
    const int*   v_i         = (const int*)d_in[2];
    const int*   v_j         = (const int*)d_in[3];
    const int*   negs        = (const int*)d_in[4];

    const int batch  = in_sizes[2];                 // 131072
    const int blocks = (batch + WPB - 1) / WPB;     // 16384

    w2v_main<<<blocks, TPB>>>(second_emb, context_emb, v_i, v_j, negs, batch);
    w2v_reduce<<<1, 1024>>>((float*)d_out, 1.0f / (float)batch);
}